// round 10
// baseline (speedup 1.0000x reference)
#include <cuda_runtime.h>
#include <math.h>

#define B_DIM 2048
#define T_DIM 256
#define IN_DIM 128
#define H_DIM 256
#define G3 768   // 3*H

typedef unsigned long long ull;

// Scratch (static device arrays)
__device__ float g_gi[(size_t)B_DIM * T_DIM * G3];   // [B][T][768]
// Packed W: for k2 in [0,128), pair p in [0,384):
//   Wq[k2*1536 + p*4 + {0,1,2,3}] = Whh[2p][2k2], Whh[2p+1][2k2],
//                                   Whh[2p][2k2+1], Whh[2p+1][2k2+1]
__device__ float g_Wq[(size_t)(H_DIM / 2) * 2 * G3];

// ---------------------------------------------------------------------------
// Packed fp32x2 helpers. Each half is an independent IEEE fp32 FMA with
// single rounding -> bit-identical to scalar FFMA chains.
// ---------------------------------------------------------------------------
__device__ __forceinline__ ull dup2(float x) {
    ull r; asm("mov.b64 %0, {%1, %1};" : "=l"(r) : "f"(x)); return r;
}
__device__ __forceinline__ void ffma2(ull &d, ull a, ull b) {
    asm("fma.rn.f32x2 %0, %1, %2, %0;" : "+l"(d) : "l"(a), "l"(b));
}
__device__ __forceinline__ void unpack2(ull v, float &x, float &y) {
    asm("mov.b64 {%0, %1}, %2;" : "=f"(x), "=f"(y) : "l"(v));
}

// ---------------------------------------------------------------------------
// XLA f32 tanh (Eigen rational poly, FMA-contracted) — bit-exact vs reference
// ---------------------------------------------------------------------------
__device__ __forceinline__ float tanh_xla(float x) {
    const float kClamp = 7.90531110763549805f;
    float xc = fminf(fmaxf(x, -kClamp), kClamp);

    const float a1  = 4.89352455891786e-03f;
    const float a3  = 6.37261928875436e-04f;
    const float a5  = 1.48572235717979e-05f;
    const float a7  = 5.12229709037114e-08f;
    const float a9  = -8.60467152213735e-11f;
    const float a11 = 2.00018790482477e-13f;
    const float a13 = -2.76076847742355e-16f;
    const float b0  = 4.89352518554385e-03f;
    const float b2  = 2.26843463243900e-03f;
    const float b4  = 1.18534705686654e-04f;
    const float b6  = 1.19825839466702e-06f;

    float x2 = __fmul_rn(xc, xc);

    float p = a13;
    p = fmaf(x2, p, a11);
    p = fmaf(x2, p, a9);
    p = fmaf(x2, p, a7);
    p = fmaf(x2, p, a5);
    p = fmaf(x2, p, a3);
    p = fmaf(x2, p, a1);
    float num = __fmul_rn(xc, p);

    float q = b6;
    q = fmaf(x2, q, b4);
    q = fmaf(x2, q, b2);
    q = fmaf(x2, q, b0);

    float ratio = __fdiv_rn(num, q);
    return (fabsf(x) < 0.0004f) ? x : ratio;
}

__device__ __forceinline__ float sigmoid_xla(float x) {
    float t = tanh_xla(__fmul_rn(0.5f, x));
    return fmaf(0.5f, t, 0.5f);
}

// ---------------------------------------------------------------------------
// One-off W packer (see g_Wq layout comment)
// ---------------------------------------------------------------------------
__global__ void pack_wq(const float* __restrict__ Whh, float* __restrict__ Wq)
{
    int idx = blockIdx.x * blockDim.x + threadIdx.x;   // 0..196607
    int k2 = idx / 1536;
    int r  = idx - k2 * 1536;
    int p  = r >> 2;
    int j  = r & 3;
    int n  = 2 * p + (j & 1);
    int k  = 2 * k2 + (j >> 1);
    Wq[idx] = Whh[(size_t)n * H_DIM + k];
}

// ---------------------------------------------------------------------------
// gi GEMM (r6-proven, verbatim): C[M,768] = A[M,K] * W[768,K]^T, FFMA2 m-pairs
// ---------------------------------------------------------------------------
template<int K>
__global__ __launch_bounds__(128) void sgemm_nt2(
    const float* __restrict__ A, const float* __restrict__ W, float* __restrict__ C)
{
    __shared__ alignas(8) float As[16][66];
    __shared__ float Ws[16][66];

    const int tid = threadIdx.x;
    const int tn  = tid & 15;
    const int tm  = tid >> 4;
    const size_t m0 = (size_t)blockIdx.x * 64;
    const int    n0 = blockIdx.y * 64;

    const int lk = tid & 15;
    const int lm = tid >> 4;

    ull acc[4][4];
#pragma unroll
    for (int p = 0; p < 4; p++)
#pragma unroll
        for (int j = 0; j < 4; j++) acc[p][j] = 0ULL;

#pragma unroll 1
    for (int k0 = 0; k0 < K; k0 += 16) {
#pragma unroll
        for (int it = 0; it < 8; it++) {
            int m = lm + it * 8;
            As[lk][m] = A[(m0 + m) * K + (k0 + lk)];
            Ws[lk][m] = W[(size_t)(n0 + m) * K + (k0 + lk)];
        }
        __syncthreads();
#pragma unroll
        for (int kk = 0; kk < 16; kk++) {
            ull a[4];
#pragma unroll
            for (int p = 0; p < 4; p++)
                a[p] = *(const ull*)&As[kk][tm * 8 + 2 * p];
#pragma unroll
            for (int j = 0; j < 4; j++) {
                ull w2 = dup2(Ws[kk][tn * 4 + j]);
#pragma unroll
                for (int p = 0; p < 4; p++)
                    ffma2(acc[p][j], a[p], w2);
            }
        }
        __syncthreads();
    }

#pragma unroll
    for (int p = 0; p < 4; p++) {
        size_t r0 = m0 + tm * 8 + 2 * p;
#pragma unroll
        for (int j = 0; j < 4; j++) {
            float lo, hi;
            unpack2(acc[p][j], lo, hi);
            C[r0 * G3 + (n0 + tn * 4 + j)]       = lo;
            C[(r0 + 1) * G3 + (n0 + tn * 4 + j)] = hi;
        }
    }
}

// ---------------------------------------------------------------------------
// Persistent GRU: 128 blocks x 512 threads, each block owns 16 batch rows
// for all 256 steps. h lives in smem PRE-DUPLICATED (h,h); W streams from L2
// as packed LDG.128 (2 kk per load); accumulators pack (hc, hc+1).
// Thread: tn = tid & 127 -> hc pair {2tn, 2tn+1}; mg = tid >> 7 -> rows
// mg*4 .. mg*4+3. Per 2kk: 3 LDG.128 + 8 bcast LDS.64 + 24 FFMA2.
// ---------------------------------------------------------------------------
#define MB 16
#define HD_STRIDE 17                          // ulls per h row (k), padded
#define SM_H_ULLS (H_DIM * HD_STRIDE)         // 4352
#define SM_GI_FLOATS (MB * G3)                // 12288
#define SM_TOTAL_BYTES (SM_H_ULLS * 8 + SM_GI_FLOATS * 4)   // 83968

__global__ __launch_bounds__(512, 1) void gru_persist(
    const float* __restrict__ gi_all,   // [B][T][768]
    const float* __restrict__ Wq,       // packed, see above
    const float* __restrict__ b_ih, const float* __restrict__ b_hh,
    float* __restrict__ out)            // [B][256]
{
    extern __shared__ ull sm[];
    ull*   h_dup = sm;                         // [256][HD_STRIDE] (h,h) pairs
    float* gi_sm = (float*)(sm + SM_H_ULLS);   // [16][768]

    const int tid = threadIdx.x;
    const int tn  = tid & 127;          // hc pair index: hc0 = 2*tn
    const int mg  = tid >> 7;           // 0..3 -> rows mg*4 .. mg*4+3
    const int hc0 = 2 * tn;
    const int mg4 = mg * 4;
    const int m0  = blockIdx.x * MB;

    // zero h tile
    for (int i = tid; i < SM_H_ULLS; i += 512) h_dup[i] = 0ULL;

    // biases for this thread's two hc columns
    float bir[2], biz[2], bin[2], bhr[2], bhz[2], bhn[2];
#pragma unroll
    for (int w = 0; w < 2; w++) {
        int hc = hc0 + w;
        bir[w] = b_ih[hc]; biz[w] = b_ih[hc + H_DIM]; bin[w] = b_ih[hc + 2 * H_DIM];
        bhr[w] = b_hh[hc]; bhz[w] = b_hh[hc + H_DIM]; bhn[w] = b_hh[hc + 2 * H_DIM];
    }

    float hprev[4][2];                  // [row][hw]
#pragma unroll
    for (int r = 0; r < 4; r++) { hprev[r][0] = 0.0f; hprev[r][1] = 0.0f; }

    // W pointers for the 3 gates (pair p = g*128 + tn)
    const float* wq_r = Wq + (size_t)(0 * 128 + tn) * 4;
    const float* wq_z = Wq + (size_t)(1 * 128 + tn) * 4;
    const float* wq_n = Wq + (size_t)(2 * 128 + tn) * 4;

    __syncthreads();

    for (int t = 0; t < T_DIM; t++) {
        // ---- prefetch this step's gi tile (16 x 768 = 48KB) via cp.async ----
#pragma unroll
        for (int i = 0; i < 6; i++) {
            int c  = tid + i * 512;          // 0..3071 16B chunks
            int mm = c / 192;
            int j  = c - mm * 192;
            const float* src = gi_all + ((size_t)(m0 + mm) * T_DIM + t) * G3 + j * 4;
            float* dst = gi_sm + mm * G3 + j * 4;
            unsigned daddr = (unsigned)__cvta_generic_to_shared(dst);
            asm volatile("cp.async.ca.shared.global [%0], [%1], 16;"
                         :: "r"(daddr), "l"(src) : "memory");
        }
        asm volatile("cp.async.commit_group;" ::: "memory");

        // ---- recurrent GEMM: accs pack (hc0, hc0+1); serial ascending k ----
        ull acc[3][4];   // [gate][row]
#pragma unroll
        for (int g = 0; g < 3; g++)
#pragma unroll
            for (int r = 0; r < 4; r++) acc[g][r] = 0ULL;

#pragma unroll 4
        for (int k2 = 0; k2 < H_DIM / 2; k2++) {
            const size_t off = (size_t)k2 * 1536;
            longlong2 vr = *(const longlong2*)(wq_r + off);
            longlong2 vz = *(const longlong2*)(wq_z + off);
            longlong2 vn = *(const longlong2*)(wq_n + off);
            const ull* h0 = h_dup + (2 * k2) * HD_STRIDE + mg4;
            const ull* h1 = h0 + HD_STRIDE;
#pragma unroll
            for (int r = 0; r < 4; r++) {
                ull a = h0[r];
                ffma2(acc[0][r], a, (ull)vr.x);
                ffma2(acc[1][r], a, (ull)vz.x);
                ffma2(acc[2][r], a, (ull)vn.x);
            }
#pragma unroll
            for (int r = 0; r < 4; r++) {
                ull a = h1[r];
                ffma2(acc[0][r], a, (ull)vr.y);
                ffma2(acc[1][r], a, (ull)vz.y);
                ffma2(acc[2][r], a, (ull)vn.y);
            }
        }

        asm volatile("cp.async.wait_group 0;" ::: "memory");
        __syncthreads();   // gi ready; all h_dup reads of this step done

        // ---- epilogue: exact XLA combine + sign (bit-exact, unchanged) ----
#pragma unroll
        for (int r = 0; r < 4; r++) {
            float gr2[2], gz2[2], gn2[2];
            unpack2(acc[0][r], gr2[0], gr2[1]);
            unpack2(acc[1][r], gz2[0], gz2[1]);
            unpack2(acc[2][r], gn2[0], gn2[1]);
            const float* gi = gi_sm + (mg4 + r) * G3;
#pragma unroll
            for (int hw = 0; hw < 2; hw++) {
                const int hc = hc0 + hw;

                float i_r = __fadd_rn(gi[hc],             bir[hw]);
                float i_z = __fadd_rn(gi[hc +     H_DIM], biz[hw]);
                float i_n = __fadd_rn(gi[hc + 2 * H_DIM], bin[hw]);
                float h_r = __fadd_rn(gr2[hw], bhr[hw]);
                float h_z = __fadd_rn(gz2[hw], bhz[hw]);
                float h_n = __fadd_rn(gn2[hw], bhn[hw]);

                float rg = sigmoid_xla(__fadd_rn(i_r, h_r));
                float zg = sigmoid_xla(__fadd_rn(i_z, h_z));
                float ng = tanh_xla(fmaf(rg, h_n, i_n));

                float omz  = __fsub_rn(1.0f, zg);
                float zh   = __fmul_rn(zg, hprev[r][hw]);
                float hnew = fmaf(omz, ng, zh);

                float s = (hnew > 0.0f) ? 1.0f : ((hnew < 0.0f) ? -1.0f : 0.0f);
                hprev[r][hw] = s;

                // write duplicated h for next step's GEMM
                h_dup[(size_t)hc * HD_STRIDE + mg4 + r] = dup2(s);

                if (t == T_DIM - 1)
                    out[(size_t)(m0 + mg4 + r) * H_DIM + hc] = s;
            }
        }

        __syncthreads();   // new h visible before next step's GEMM
    }
}

extern "C" void kernel_launch(void* const* d_in, const int* in_sizes, int n_in,
                              void* d_out, int out_size)
{
    const float* x   = (const float*)d_in[0];  // [2048, 256, 128]
    const float* Wih = (const float*)d_in[1];  // [768, 128]
    const float* Whh = (const float*)d_in[2];  // [768, 256]
    const float* bih = (const float*)d_in[3];  // [768]
    const float* bhh = (const float*)d_in[4];  // [768]
    float* out = (float*)d_out;                // [2048, 256]

    float *gi_p, *wq_p;
    cudaGetSymbolAddress((void**)&gi_p, g_gi);
    cudaGetSymbolAddress((void**)&wq_p, g_Wq);

    cudaFuncSetAttribute(gru_persist, cudaFuncAttributeMaxDynamicSharedMemorySize,
                         SM_TOTAL_BYTES);

    // Prep: pack Whh into the LDG.128-friendly layout.
    pack_wq<<<(H_DIM / 2 * 2 * G3) / 256, 256>>>(Whh, wq_p);

    // Phase 1: gi = X @ W_ih^T  (M = B*T = 524288, K = 128) -> [B][T][768]
    {
        dim3 grid((B_DIM * T_DIM) / 64, G3 / 64);
        sgemm_nt2<IN_DIM><<<grid, 128>>>(x, Wih, gi_p);
    }

    // Phase 2: persistent recurrence — one kernel for all 256 steps.
    gru_persist<<<B_DIM / MB, 512, SM_TOTAL_BYTES>>>(gi_p, wq_p, bih, bhh, out);
}

// round 11
// speedup vs baseline: 1.5474x; 1.5474x over previous
#include <cuda_runtime.h>
#include <math.h>

#define B_DIM 2048
#define T_DIM 256
#define IN_DIM 128
#define H_DIM 256
#define G3 768   // 3*H

typedef unsigned long long ull;

// Scratch (static device arrays)
__device__ float g_gi[(size_t)B_DIM * T_DIM * G3];   // [B][T][768]
// Packed W: for k2 in [0,128), pair p in [0,384):
//   Wq[k2*1536 + p*4 + {0,1,2,3}] = Whh[2p][2k2], Whh[2p+1][2k2],
//                                   Whh[2p][2k2+1], Whh[2p+1][2k2+1]
__device__ float g_Wq[(size_t)(H_DIM / 2) * 2 * G3];

// ---------------------------------------------------------------------------
// Packed fp32x2 helpers. Each half is an independent IEEE fp32 FMA with
// single rounding -> bit-identical to scalar FFMA chains.
// ---------------------------------------------------------------------------
__device__ __forceinline__ ull dup2(float x) {
    ull r; asm("mov.b64 %0, {%1, %1};" : "=l"(r) : "f"(x)); return r;
}
__device__ __forceinline__ void ffma2(ull &d, ull a, ull b) {
    asm("fma.rn.f32x2 %0, %1, %2, %0;" : "+l"(d) : "l"(a), "l"(b));
}
__device__ __forceinline__ void unpack2(ull v, float &x, float &y) {
    asm("mov.b64 {%0, %1}, %2;" : "=f"(x), "=f"(y) : "l"(v));
}

// ---------------------------------------------------------------------------
// XLA f32 tanh (Eigen rational poly, FMA-contracted) — bit-exact vs reference
// ---------------------------------------------------------------------------
__device__ __forceinline__ float tanh_xla(float x) {
    const float kClamp = 7.90531110763549805f;
    float xc = fminf(fmaxf(x, -kClamp), kClamp);

    const float a1  = 4.89352455891786e-03f;
    const float a3  = 6.37261928875436e-04f;
    const float a5  = 1.48572235717979e-05f;
    const float a7  = 5.12229709037114e-08f;
    const float a9  = -8.60467152213735e-11f;
    const float a11 = 2.00018790482477e-13f;
    const float a13 = -2.76076847742355e-16f;
    const float b0  = 4.89352518554385e-03f;
    const float b2  = 2.26843463243900e-03f;
    const float b4  = 1.18534705686654e-04f;
    const float b6  = 1.19825839466702e-06f;

    float x2 = __fmul_rn(xc, xc);

    float p = a13;
    p = fmaf(x2, p, a11);
    p = fmaf(x2, p, a9);
    p = fmaf(x2, p, a7);
    p = fmaf(x2, p, a5);
    p = fmaf(x2, p, a3);
    p = fmaf(x2, p, a1);
    float num = __fmul_rn(xc, p);

    float q = b6;
    q = fmaf(x2, q, b4);
    q = fmaf(x2, q, b2);
    q = fmaf(x2, q, b0);

    float ratio = __fdiv_rn(num, q);
    return (fabsf(x) < 0.0004f) ? x : ratio;
}

__device__ __forceinline__ float sigmoid_xla(float x) {
    float t = tanh_xla(__fmul_rn(0.5f, x));
    return fmaf(0.5f, t, 0.5f);
}

// ---------------------------------------------------------------------------
// One-off W packer (see g_Wq layout comment)
// ---------------------------------------------------------------------------
__global__ void pack_wq(const float* __restrict__ Whh, float* __restrict__ Wq)
{
    int idx = blockIdx.x * blockDim.x + threadIdx.x;   // 0..196607
    int k2 = idx / 1536;
    int r  = idx - k2 * 1536;
    int p  = r >> 2;
    int j  = r & 3;
    int n  = 2 * p + (j & 1);
    int k  = 2 * k2 + (j >> 1);
    Wq[idx] = Whh[(size_t)n * H_DIM + k];
}

// ---------------------------------------------------------------------------
// gi GEMM (r6-proven, verbatim): C[M,768] = A[M,K] * W[768,K]^T, FFMA2 m-pairs
// ---------------------------------------------------------------------------
template<int K>
__global__ __launch_bounds__(128) void sgemm_nt2(
    const float* __restrict__ A, const float* __restrict__ W, float* __restrict__ C)
{
    __shared__ alignas(8) float As[16][66];
    __shared__ float Ws[16][66];

    const int tid = threadIdx.x;
    const int tn  = tid & 15;
    const int tm  = tid >> 4;
    const size_t m0 = (size_t)blockIdx.x * 64;
    const int    n0 = blockIdx.y * 64;

    const int lk = tid & 15;
    const int lm = tid >> 4;

    ull acc[4][4];
#pragma unroll
    for (int p = 0; p < 4; p++)
#pragma unroll
        for (int j = 0; j < 4; j++) acc[p][j] = 0ULL;

#pragma unroll 1
    for (int k0 = 0; k0 < K; k0 += 16) {
#pragma unroll
        for (int it = 0; it < 8; it++) {
            int m = lm + it * 8;
            As[lk][m] = A[(m0 + m) * K + (k0 + lk)];
            Ws[lk][m] = W[(size_t)(n0 + m) * K + (k0 + lk)];
        }
        __syncthreads();
#pragma unroll
        for (int kk = 0; kk < 16; kk++) {
            ull a[4];
#pragma unroll
            for (int p = 0; p < 4; p++)
                a[p] = *(const ull*)&As[kk][tm * 8 + 2 * p];
#pragma unroll
            for (int j = 0; j < 4; j++) {
                ull w2 = dup2(Ws[kk][tn * 4 + j]);
#pragma unroll
                for (int p = 0; p < 4; p++)
                    ffma2(acc[p][j], a[p], w2);
            }
        }
        __syncthreads();
    }

#pragma unroll
    for (int p = 0; p < 4; p++) {
        size_t r0 = m0 + tm * 8 + 2 * p;
#pragma unroll
        for (int j = 0; j < 4; j++) {
            float lo, hi;
            unpack2(acc[p][j], lo, hi);
            C[r0 * G3 + (n0 + tn * 4 + j)]       = lo;
            C[(r0 + 1) * G3 + (n0 + tn * 4 + j)] = hi;
        }
    }
}

// ---------------------------------------------------------------------------
// Persistent GRU: 128 blocks x 256 threads (r9 geometry), hc-packed accs
// (r10 packing). Each block owns 16 batch rows for all 256 steps.
//   - acc packs (hc0, hc0+1): B-operand = plain float2 of adjacent W cols
//     via one LDG.128 per gate per 2kk (no dup-movs in the loop).
//   - A-operand = dup'd h, stored pre-duplicated in smem (written once per
//     step, read as warp-broadcast LDS.128: ~1 crossbar cycle each).
// Thread: tn = tid & 127 -> hc pair {2tn, 2tn+1}; mg = tid >> 7 -> rows
// mg*8 .. mg*8+7. Per 2kk per thread: 3 LDG.128 + 8 LDS.128 + 48 FFMA2.
// ---------------------------------------------------------------------------
#define MB 16
#define HD_STRIDE 18                          // ulls per h k-row (16B aligned)
#define SM_H_ULLS (H_DIM * HD_STRIDE)         // 4608
#define SM_GI_FLOATS (MB * G3)                // 12288
#define SM_TOTAL_BYTES (SM_H_ULLS * 8 + SM_GI_FLOATS * 4)   // 86016

__global__ __launch_bounds__(256, 1) void gru_persist(
    const float* __restrict__ gi_all,   // [B][T][768]
    const float* __restrict__ Wq,       // packed, see above
    const float* __restrict__ b_ih, const float* __restrict__ b_hh,
    float* __restrict__ out)            // [B][256]
{
    extern __shared__ ull sm[];
    ull*   h_dup = sm;                         // [256][HD_STRIDE] (h,h) pairs
    float* gi_sm = (float*)(sm + SM_H_ULLS);   // [16][768]

    const int tid = threadIdx.x;
    const int tn  = tid & 127;          // hc pair index: hc0 = 2*tn
    const int mg  = tid >> 7;           // 0/1 -> rows mg*8 .. mg*8+7
    const int hc0 = 2 * tn;
    const int mg8 = mg * 8;
    const int m0  = blockIdx.x * MB;

    // zero h tile
    for (int i = tid; i < SM_H_ULLS; i += 256) h_dup[i] = 0ULL;

    // biases for this thread's two hc columns
    float bir[2], biz[2], bin[2], bhr[2], bhz[2], bhn[2];
#pragma unroll
    for (int w = 0; w < 2; w++) {
        int hc = hc0 + w;
        bir[w] = b_ih[hc]; biz[w] = b_ih[hc + H_DIM]; bin[w] = b_ih[hc + 2 * H_DIM];
        bhr[w] = b_hh[hc]; bhz[w] = b_hh[hc + H_DIM]; bhn[w] = b_hh[hc + 2 * H_DIM];
    }

    float hprev[8][2];                  // [row][hw]
#pragma unroll
    for (int r = 0; r < 8; r++) { hprev[r][0] = 0.0f; hprev[r][1] = 0.0f; }

    // W pointers for the 3 gates (pair p = g*128 + tn)
    const float* wq_r = Wq + (size_t)(0 * 128 + tn) * 4;
    const float* wq_z = Wq + (size_t)(1 * 128 + tn) * 4;
    const float* wq_n = Wq + (size_t)(2 * 128 + tn) * 4;

    __syncthreads();

    for (int t = 0; t < T_DIM; t++) {
        // ---- prefetch this step's gi tile (16 x 768 = 48KB) via cp.async ----
#pragma unroll
        for (int i = 0; i < 12; i++) {
            int c  = tid + i * 256;          // 0..3071 16B chunks
            int mm = c / 192;
            int j  = c - mm * 192;
            const float* src = gi_all + ((size_t)(m0 + mm) * T_DIM + t) * G3 + j * 4;
            float* dst = gi_sm + mm * G3 + j * 4;
            unsigned daddr = (unsigned)__cvta_generic_to_shared(dst);
            asm volatile("cp.async.ca.shared.global [%0], [%1], 16;"
                         :: "r"(daddr), "l"(src) : "memory");
        }
        asm volatile("cp.async.commit_group;" ::: "memory");

        // ---- recurrent GEMM: accs pack (hc0, hc0+1); serial ascending k ----
        ull acc[3][8];   // [gate][row]
#pragma unroll
        for (int g = 0; g < 3; g++)
#pragma unroll
            for (int r = 0; r < 8; r++) acc[g][r] = 0ULL;

#pragma unroll 4
        for (int k2 = 0; k2 < H_DIM / 2; k2++) {
            const size_t off = (size_t)k2 * 1536;
            longlong2 vr = *(const longlong2*)(wq_r + off);
            longlong2 vz = *(const longlong2*)(wq_z + off);
            longlong2 vn = *(const longlong2*)(wq_n + off);

            const ulonglong2* h0 =
                (const ulonglong2*)(h_dup + (size_t)(2 * k2) * HD_STRIDE + mg8);
            const ulonglong2* h1 =
                (const ulonglong2*)(h_dup + (size_t)(2 * k2 + 1) * HD_STRIDE + mg8);

            // kk = 2*k2
            {
                ulonglong2 p0 = h0[0], p1 = h0[1], p2 = h0[2], p3 = h0[3];
                ffma2(acc[0][0], p0.x, (ull)vr.x); ffma2(acc[1][0], p0.x, (ull)vz.x); ffma2(acc[2][0], p0.x, (ull)vn.x);
                ffma2(acc[0][1], p0.y, (ull)vr.x); ffma2(acc[1][1], p0.y, (ull)vz.x); ffma2(acc[2][1], p0.y, (ull)vn.x);
                ffma2(acc[0][2], p1.x, (ull)vr.x); ffma2(acc[1][2], p1.x, (ull)vz.x); ffma2(acc[2][2], p1.x, (ull)vn.x);
                ffma2(acc[0][3], p1.y, (ull)vr.x); ffma2(acc[1][3], p1.y, (ull)vz.x); ffma2(acc[2][3], p1.y, (ull)vn.x);
                ffma2(acc[0][4], p2.x, (ull)vr.x); ffma2(acc[1][4], p2.x, (ull)vz.x); ffma2(acc[2][4], p2.x, (ull)vn.x);
                ffma2(acc[0][5], p2.y, (ull)vr.x); ffma2(acc[1][5], p2.y, (ull)vz.x); ffma2(acc[2][5], p2.y, (ull)vn.x);
                ffma2(acc[0][6], p3.x, (ull)vr.x); ffma2(acc[1][6], p3.x, (ull)vz.x); ffma2(acc[2][6], p3.x, (ull)vn.x);
                ffma2(acc[0][7], p3.y, (ull)vr.x); ffma2(acc[1][7], p3.y, (ull)vz.x); ffma2(acc[2][7], p3.y, (ull)vn.x);
            }
            // kk = 2*k2 + 1
            {
                ulonglong2 p0 = h1[0], p1 = h1[1], p2 = h1[2], p3 = h1[3];
                ffma2(acc[0][0], p0.x, (ull)vr.y); ffma2(acc[1][0], p0.x, (ull)vz.y); ffma2(acc[2][0], p0.x, (ull)vn.y);
                ffma2(acc[0][1], p0.y, (ull)vr.y); ffma2(acc[1][1], p0.y, (ull)vz.y); ffma2(acc[2][1], p0.y, (ull)vn.y);
                ffma2(acc[0][2], p1.x, (ull)vr.y); ffma2(acc[1][2], p1.x, (ull)vz.y); ffma2(acc[2][2], p1.x, (ull)vn.y);
                ffma2(acc[0][3], p1.y, (ull)vr.y); ffma2(acc[1][3], p1.y, (ull)vz.y); ffma2(acc[2][3], p1.y, (ull)vn.y);
                ffma2(acc[0][4], p2.x, (ull)vr.y); ffma2(acc[1][4], p2.x, (ull)vz.y); ffma2(acc[2][4], p2.x, (ull)vn.y);
                ffma2(acc[0][5], p2.y, (ull)vr.y); ffma2(acc[1][5], p2.y, (ull)vz.y); ffma2(acc[2][5], p2.y, (ull)vn.y);
                ffma2(acc[0][6], p3.x, (ull)vr.y); ffma2(acc[1][6], p3.x, (ull)vz.y); ffma2(acc[2][6], p3.x, (ull)vn.y);
                ffma2(acc[0][7], p3.y, (ull)vr.y); ffma2(acc[1][7], p3.y, (ull)vz.y); ffma2(acc[2][7], p3.y, (ull)vn.y);
            }
        }

        asm volatile("cp.async.wait_group 0;" ::: "memory");
        __syncthreads();   // gi ready; all h_dup reads of this step done

        // ---- epilogue: exact XLA combine + sign (bit-exact, unchanged) ----
#pragma unroll
        for (int r = 0; r < 8; r++) {
            float gr2[2], gz2[2], gn2[2];
            unpack2(acc[0][r], gr2[0], gr2[1]);
            unpack2(acc[1][r], gz2[0], gz2[1]);
            unpack2(acc[2][r], gn2[0], gn2[1]);
            const float* gi = gi_sm + (mg8 + r) * G3;
#pragma unroll
            for (int hw = 0; hw < 2; hw++) {
                const int hc = hc0 + hw;

                float i_r = __fadd_rn(gi[hc],             bir[hw]);
                float i_z = __fadd_rn(gi[hc +     H_DIM], biz[hw]);
                float i_n = __fadd_rn(gi[hc + 2 * H_DIM], bin[hw]);
                float h_r = __fadd_rn(gr2[hw], bhr[hw]);
                float h_z = __fadd_rn(gz2[hw], bhz[hw]);
                float h_n = __fadd_rn(gn2[hw], bhn[hw]);

                float rg = sigmoid_xla(__fadd_rn(i_r, h_r));
                float zg = sigmoid_xla(__fadd_rn(i_z, h_z));
                float ng = tanh_xla(fmaf(rg, h_n, i_n));

                float omz  = __fsub_rn(1.0f, zg);
                float zh   = __fmul_rn(zg, hprev[r][hw]);
                float hnew = fmaf(omz, ng, zh);

                float s = (hnew > 0.0f) ? 1.0f : ((hnew < 0.0f) ? -1.0f : 0.0f);
                hprev[r][hw] = s;

                // write duplicated h for next step's GEMM
                h_dup[(size_t)hc * HD_STRIDE + mg8 + r] = dup2(s);

                if (t == T_DIM - 1)
                    out[(size_t)(m0 + mg8 + r) * H_DIM + hc] = s;
            }
        }

        __syncthreads();   // new h visible before next step's GEMM
    }
}

extern "C" void kernel_launch(void* const* d_in, const int* in_sizes, int n_in,
                              void* d_out, int out_size)
{
    const float* x   = (const float*)d_in[0];  // [2048, 256, 128]
    const float* Wih = (const float*)d_in[1];  // [768, 128]
    const float* Whh = (const float*)d_in[2];  // [768, 256]
    const float* bih = (const float*)d_in[3];  // [768]
    const float* bhh = (const float*)d_in[4];  // [768]
    float* out = (float*)d_out;                // [2048, 256]

    float *gi_p, *wq_p;
    cudaGetSymbolAddress((void**)&gi_p, g_gi);
    cudaGetSymbolAddress((void**)&wq_p, g_Wq);

    cudaFuncSetAttribute(gru_persist, cudaFuncAttributeMaxDynamicSharedMemorySize,
                         SM_TOTAL_BYTES);

    // Prep: pack Whh into the LDG.128-friendly layout.
    pack_wq<<<(H_DIM / 2 * 2 * G3) / 256, 256>>>(Whh, wq_p);

    // Phase 1: gi = X @ W_ih^T  (M = B*T = 524288, K = 128) -> [B][T][768]
    {
        dim3 grid((B_DIM * T_DIM) / 64, G3 / 64);
        sgemm_nt2<IN_DIM><<<grid, 128>>>(x, Wih, gi_p);
    }

    // Phase 2: persistent recurrence — one kernel for all 256 steps.
    gru_persist<<<B_DIM / MB, 256, SM_TOTAL_BYTES>>>(gi_p, wq_p, bih, bhh, out);
}

// round 13
// speedup vs baseline: 1.6737x; 1.0816x over previous
#include <cuda_runtime.h>
#include <math.h>

#define B_DIM 2048
#define T_DIM 256
#define IN_DIM 128
#define H_DIM 256
#define G3 768   // 3*H

typedef unsigned long long ull;

// Scratch (static device arrays)
__device__ float g_gi[(size_t)B_DIM * T_DIM * G3];   // [B][T][768]
// Packed W: for k2 in [0,128), pair p in [0,384):
//   Wq[k2*1536 + p*4 + {0,1,2,3}] = Whh[2p][2k2], Whh[2p+1][2k2],
//                                   Whh[2p][2k2+1], Whh[2p+1][2k2+1]
__device__ float g_Wq[(size_t)(H_DIM / 2) * 2 * G3];

// ---------------------------------------------------------------------------
// Packed fp32x2 helpers. Each half is an independent IEEE fp32 FMA with
// single rounding -> bit-identical to scalar FFMA chains.
// ---------------------------------------------------------------------------
__device__ __forceinline__ ull dup2(float x) {
    ull r; asm("mov.b64 %0, {%1, %1};" : "=l"(r) : "f"(x)); return r;
}
__device__ __forceinline__ void ffma2(ull &d, ull a, ull b) {
    asm("fma.rn.f32x2 %0, %1, %2, %0;" : "+l"(d) : "l"(a), "l"(b));
}
__device__ __forceinline__ void unpack2(ull v, float &x, float &y) {
    asm("mov.b64 {%0, %1}, %2;" : "=f"(x), "=f"(y) : "l"(v));
}

// ---------------------------------------------------------------------------
// XLA f32 tanh (Eigen rational poly, FMA-contracted) — bit-exact vs reference
// ---------------------------------------------------------------------------
__device__ __forceinline__ float tanh_xla(float x) {
    const float kClamp = 7.90531110763549805f;
    float xc = fminf(fmaxf(x, -kClamp), kClamp);

    const float a1  = 4.89352455891786e-03f;
    const float a3  = 6.37261928875436e-04f;
    const float a5  = 1.48572235717979e-05f;
    const float a7  = 5.12229709037114e-08f;
    const float a9  = -8.60467152213735e-11f;
    const float a11 = 2.00018790482477e-13f;
    const float a13 = -2.76076847742355e-16f;
    const float b0  = 4.89352518554385e-03f;
    const float b2  = 2.26843463243900e-03f;
    const float b4  = 1.18534705686654e-04f;
    const float b6  = 1.19825839466702e-06f;

    float x2 = __fmul_rn(xc, xc);

    float p = a13;
    p = fmaf(x2, p, a11);
    p = fmaf(x2, p, a9);
    p = fmaf(x2, p, a7);
    p = fmaf(x2, p, a5);
    p = fmaf(x2, p, a3);
    p = fmaf(x2, p, a1);
    float num = __fmul_rn(xc, p);

    float q = b6;
    q = fmaf(x2, q, b4);
    q = fmaf(x2, q, b2);
    q = fmaf(x2, q, b0);

    float ratio = __fdiv_rn(num, q);
    return (fabsf(x) < 0.0004f) ? x : ratio;
}

__device__ __forceinline__ float sigmoid_xla(float x) {
    float t = tanh_xla(__fmul_rn(0.5f, x));
    return fmaf(0.5f, t, 0.5f);
}

// ---------------------------------------------------------------------------
// One-off W packer (see g_Wq layout comment)
// ---------------------------------------------------------------------------
__global__ void pack_wq(const float* __restrict__ Whh, float* __restrict__ Wq)
{
    int idx = blockIdx.x * blockDim.x + threadIdx.x;   // 0..196607
    int k2 = idx / 1536;
    int r  = idx - k2 * 1536;
    int p  = r >> 2;
    int j  = r & 3;
    int n  = 2 * p + (j & 1);
    int k  = 2 * k2 + (j >> 1);
    Wq[idx] = Whh[(size_t)n * H_DIM + k];
}

// ---------------------------------------------------------------------------
// gi GEMM (r6-proven, verbatim): C[M,768] = A[M,K] * W[768,K]^T, FFMA2 m-pairs
// ---------------------------------------------------------------------------
template<int K>
__global__ __launch_bounds__(128) void sgemm_nt2(
    const float* __restrict__ A, const float* __restrict__ W, float* __restrict__ C)
{
    __shared__ alignas(8) float As[16][66];
    __shared__ float Ws[16][66];

    const int tid = threadIdx.x;
    const int tn  = tid & 15;
    const int tm  = tid >> 4;
    const size_t m0 = (size_t)blockIdx.x * 64;
    const int    n0 = blockIdx.y * 64;

    const int lk = tid & 15;
    const int lm = tid >> 4;

    ull acc[4][4];
#pragma unroll
    for (int p = 0; p < 4; p++)
#pragma unroll
        for (int j = 0; j < 4; j++) acc[p][j] = 0ULL;

#pragma unroll 1
    for (int k0 = 0; k0 < K; k0 += 16) {
#pragma unroll
        for (int it = 0; it < 8; it++) {
            int m = lm + it * 8;
            As[lk][m] = A[(m0 + m) * K + (k0 + lk)];
            Ws[lk][m] = W[(size_t)(n0 + m) * K + (k0 + lk)];
        }
        __syncthreads();
#pragma unroll
        for (int kk = 0; kk < 16; kk++) {
            ull a[4];
#pragma unroll
            for (int p = 0; p < 4; p++)
                a[p] = *(const ull*)&As[kk][tm * 8 + 2 * p];
#pragma unroll
            for (int j = 0; j < 4; j++) {
                ull w2 = dup2(Ws[kk][tn * 4 + j]);
#pragma unroll
                for (int p = 0; p < 4; p++)
                    ffma2(acc[p][j], a[p], w2);
            }
        }
        __syncthreads();
    }

#pragma unroll
    for (int p = 0; p < 4; p++) {
        size_t r0 = m0 + tm * 8 + 2 * p;
#pragma unroll
        for (int j = 0; j < 4; j++) {
            float lo, hi;
            unpack2(acc[p][j], lo, hi);
            C[r0 * G3 + (n0 + tn * 4 + j)]       = lo;
            C[(r0 + 1) * G3 + (n0 + tn * 4 + j)] = hi;
        }
    }
}

// ---------------------------------------------------------------------------
// Persistent GRU: 256 blocks x 256 threads, 2 blocks/SM. Each block owns 8
// batch rows for all 256 steps; r11's proven inner recipe with a 4-row
// thread tile. hc-packed accs, packed-W LDG.128, pre-dup'd h in smem.
// Thread: tn = tid & 127 -> hc pair {2tn, 2tn+1}; mg = tid >> 7 -> rows
// mg*4 .. mg*4+3. Per 2kk per thread: 3 LDG.128 + 4 LDS.128 + 24 FFMA2.
// ---------------------------------------------------------------------------
#define MB 8
#define HD_STRIDE 10                          // ulls per h k-row (16B aligned)
#define SM_H_ULLS (H_DIM * HD_STRIDE)         // 2560
#define SM_GI_FLOATS (MB * G3)                // 6144
#define SM_TOTAL_BYTES (SM_H_ULLS * 8 + SM_GI_FLOATS * 4)   // 45056

__global__ __launch_bounds__(256, 2) void gru_persist(
    const float* __restrict__ gi_all,   // [B][T][768]
    const float* __restrict__ Wq,       // packed, see above
    const float* __restrict__ b_ih, const float* __restrict__ b_hh,
    float* __restrict__ out)            // [B][256]
{
    extern __shared__ ull sm[];
    ull*   h_dup = sm;                         // [256][HD_STRIDE] (h,h) pairs
    float* gi_sm = (float*)(sm + SM_H_ULLS);   // [8][768]

    const int tid = threadIdx.x;
    const int tn  = tid & 127;          // hc pair index: hc0 = 2*tn
    const int mg  = tid >> 7;           // 0/1 -> rows mg*4 .. mg*4+3
    const int hc0 = 2 * tn;
    const int mg4 = mg * 4;
    const int m0  = blockIdx.x * MB;

    // zero h tile
    for (int i = tid; i < SM_H_ULLS; i += 256) h_dup[i] = 0ULL;

    // biases for this thread's two hc columns
    float bir[2], biz[2], bin[2], bhr[2], bhz[2], bhn[2];
#pragma unroll
    for (int w = 0; w < 2; w++) {
        int hc = hc0 + w;
        bir[w] = b_ih[hc]; biz[w] = b_ih[hc + H_DIM]; bin[w] = b_ih[hc + 2 * H_DIM];
        bhr[w] = b_hh[hc]; bhz[w] = b_hh[hc + H_DIM]; bhn[w] = b_hh[hc + 2 * H_DIM];
    }

    float hprev[4][2];                  // [row][hw]
#pragma unroll
    for (int r = 0; r < 4; r++) { hprev[r][0] = 0.0f; hprev[r][1] = 0.0f; }

    // W pointers for the 3 gates (pair p = g*128 + tn)
    const float* wq_r = Wq + (size_t)(0 * 128 + tn) * 4;
    const float* wq_z = Wq + (size_t)(1 * 128 + tn) * 4;
    const float* wq_n = Wq + (size_t)(2 * 128 + tn) * 4;

    __syncthreads();

    for (int t = 0; t < T_DIM; t++) {
        // ---- prefetch this step's gi tile (8 x 768 = 24KB) via cp.async ----
#pragma unroll
        for (int i = 0; i < 6; i++) {
            int c  = tid + i * 256;          // 0..1535 16B chunks
            int mm = c / 192;
            int j  = c - mm * 192;
            const float* src = gi_all + ((size_t)(m0 + mm) * T_DIM + t) * G3 + j * 4;
            float* dst = gi_sm + mm * G3 + j * 4;
            unsigned daddr = (unsigned)__cvta_generic_to_shared(dst);
            asm volatile("cp.async.ca.shared.global [%0], [%1], 16;"
                         :: "r"(daddr), "l"(src) : "memory");
        }
        asm volatile("cp.async.commit_group;" ::: "memory");

        // ---- recurrent GEMM: accs pack (hc0, hc0+1); serial ascending k ----
        ull acc[3][4];   // [gate][row]
#pragma unroll
        for (int g = 0; g < 3; g++)
#pragma unroll
            for (int r = 0; r < 4; r++) acc[g][r] = 0ULL;

#pragma unroll 4
        for (int k2 = 0; k2 < H_DIM / 2; k2++) {
            const size_t off = (size_t)k2 * 1536;
            longlong2 vr = *(const longlong2*)(wq_r + off);
            longlong2 vz = *(const longlong2*)(wq_z + off);
            longlong2 vn = *(const longlong2*)(wq_n + off);

            const ulonglong2* h0 =
                (const ulonglong2*)(h_dup + (size_t)(2 * k2) * HD_STRIDE + mg4);
            const ulonglong2* h1 =
                (const ulonglong2*)(h_dup + (size_t)(2 * k2 + 1) * HD_STRIDE + mg4);

            // kk = 2*k2
            {
                ulonglong2 p0 = h0[0], p1 = h0[1];
                ffma2(acc[0][0], p0.x, (ull)vr.x); ffma2(acc[1][0], p0.x, (ull)vz.x); ffma2(acc[2][0], p0.x, (ull)vn.x);
                ffma2(acc[0][1], p0.y, (ull)vr.x); ffma2(acc[1][1], p0.y, (ull)vz.x); ffma2(acc[2][1], p0.y, (ull)vn.x);
                ffma2(acc[0][2], p1.x, (ull)vr.x); ffma2(acc[1][2], p1.x, (ull)vz.x); ffma2(acc[2][2], p1.x, (ull)vn.x);
                ffma2(acc[0][3], p1.y, (ull)vr.x); ffma2(acc[1][3], p1.y, (ull)vz.x); ffma2(acc[2][3], p1.y, (ull)vn.x);
            }
            // kk = 2*k2 + 1
            {
                ulonglong2 p0 = h1[0], p1 = h1[1];
                ffma2(acc[0][0], p0.x, (ull)vr.y); ffma2(acc[1][0], p0.x, (ull)vz.y); ffma2(acc[2][0], p0.x, (ull)vn.y);
                ffma2(acc[0][1], p0.y, (ull)vr.y); ffma2(acc[1][1], p0.y, (ull)vz.y); ffma2(acc[2][1], p0.y, (ull)vn.y);
                ffma2(acc[0][2], p1.x, (ull)vr.y); ffma2(acc[1][2], p1.x, (ull)vz.y); ffma2(acc[2][2], p1.x, (ull)vn.y);
                ffma2(acc[0][3], p1.y, (ull)vr.y); ffma2(acc[1][3], p1.y, (ull)vz.y); ffma2(acc[2][3], p1.y, (ull)vn.y);
            }
        }

        asm volatile("cp.async.wait_group 0;" ::: "memory");
        __syncthreads();   // gi ready; all h_dup reads of this step done

        // ---- epilogue: exact XLA combine + sign (bit-exact, unchanged) ----
#pragma unroll
        for (int r = 0; r < 4; r++) {
            float gr2[2], gz2[2], gn2[2];
            unpack2(acc[0][r], gr2[0], gr2[1]);
            unpack2(acc[1][r], gz2[0], gz2[1]);
            unpack2(acc[2][r], gn2[0], gn2[1]);
            const float* gi = gi_sm + (mg4 + r) * G3;
#pragma unroll
            for (int hw = 0; hw < 2; hw++) {
                const int hc = hc0 + hw;

                float i_r = __fadd_rn(gi[hc],             bir[hw]);
                float i_z = __fadd_rn(gi[hc +     H_DIM], biz[hw]);
                float i_n = __fadd_rn(gi[hc + 2 * H_DIM], bin[hw]);
                float h_r = __fadd_rn(gr2[hw], bhr[hw]);
                float h_z = __fadd_rn(gz2[hw], bhz[hw]);
                float h_n = __fadd_rn(gn2[hw], bhn[hw]);

                float rg = sigmoid_xla(__fadd_rn(i_r, h_r));
                float zg = sigmoid_xla(__fadd_rn(i_z, h_z));
                float ng = tanh_xla(fmaf(rg, h_n, i_n));

                float omz  = __fsub_rn(1.0f, zg);
                float zh   = __fmul_rn(zg, hprev[r][hw]);
                float hnew = fmaf(omz, ng, zh);

                float s = (hnew > 0.0f) ? 1.0f : ((hnew < 0.0f) ? -1.0f : 0.0f);
                hprev[r][hw] = s;

                // write duplicated h for next step's GEMM
                h_dup[(size_t)hc * HD_STRIDE + mg4 + r] = dup2(s);

                if (t == T_DIM - 1)
                    out[(size_t)(m0 + mg4 + r) * H_DIM + hc] = s;
            }
        }

        __syncthreads();   // new h visible before next step's GEMM
    }
}

extern "C" void kernel_launch(void* const* d_in, const int* in_sizes, int n_in,
                              void* d_out, int out_size)
{
    const float* x   = (const float*)d_in[0];  // [2048, 256, 128]
    const float* Wih = (const float*)d_in[1];  // [768, 128]
    const float* Whh = (const float*)d_in[2];  // [768, 256]
    const float* bih = (const float*)d_in[3];  // [768]
    const float* bhh = (const float*)d_in[4];  // [768]
    float* out = (float*)d_out;                // [2048, 256]

    float *gi_p, *wq_p;
    cudaGetSymbolAddress((void**)&gi_p, g_gi);
    cudaGetSymbolAddress((void**)&wq_p, g_Wq);

    cudaFuncSetAttribute(gru_persist, cudaFuncAttributeMaxDynamicSharedMemorySize,
                         SM_TOTAL_BYTES);

    // Prep: pack Whh into the LDG.128-friendly layout.
    pack_wq<<<(H_DIM / 2 * 2 * G3) / 256, 256>>>(Whh, wq_p);

    // Phase 1: gi = X @ W_ih^T  (M = B*T = 524288, K = 128) -> [B][T][768]
    {
        dim3 grid((B_DIM * T_DIM) / 64, G3 / 64);
        sgemm_nt2<IN_DIM><<<grid, 128>>>(x, Wih, gi_p);
    }

    // Phase 2: persistent recurrence — one kernel for all 256 steps,
    // 2 blocks per SM for latency hiding.
    gru_persist<<<B_DIM / MB, 256, SM_TOTAL_BYTES>>>(gi_p, wq_p, bih, bhh, out);
}